// round 2
// baseline (speedup 1.0000x reference)
#include <cuda_runtime.h>

#define N_REL  200
#define BATCH  16384
#define DIM    128
#define N_ENT  500000
#define NSPLIT 3

// Scratch (static __device__ globals — no allocation allowed)
__device__ int g_cnt[N_REL];
__device__ int g_list[N_REL * BATCH];
__device__ int g_is64;   // 1 if data tensor is int64, 0 if int32

// Read data[elem] under either dtype, with defensive clamping.
__device__ __forceinline__ int read_idx(const void* data, int elem, int is64, int limit) {
    long long v;
    if (is64) v = ((const long long*)data)[elem];
    else      v = ((const int*)data)[elem];
    if (v < 0) v = 0;
    if (v >= limit) v = limit - 1;
    return (int)v;
}

// Zero per-launch state, detect index dtype.
__global__ void init_kernel(const unsigned int* __restrict__ data_w, float* out) {
    int t = blockIdx.x * blockDim.x + threadIdx.x;
    if (t < N_REL) g_cnt[t] = 0;
    if (t == 0) {
        out[0] = 0.0f;
        // int64 with values < 2^31  =>  all odd 32-bit words are zero.
        unsigned int acc = 0;
        #pragma unroll
        for (int k = 0; k < 32; k++) acc |= data_w[2 * k + 1];
        g_is64 = (acc == 0) ? 1 : 0;
    }
}

// Bucket batch elements by relation id.
__global__ void build_kernel(const void* __restrict__ data) {
    int b = blockIdx.x * blockDim.x + threadIdx.x;
    if (b < BATCH) {
        int is64 = g_is64;
        int r = read_idx(data, b * 5 + 2, is64, N_REL);
        int p = atomicAdd(&g_cnt[r], 1);
        g_list[r * BATCH + p] = b;
    }
}

// One block per (relation, split). Full 128x128 R tile in registers:
// thread = (column j = tid&127, row-half = tid>>7), 64 floats/thread.
__global__ __launch_bounds__(256, 2) void rescal_kernel(
    const void*  __restrict__ data,
    const float* __restrict__ ent,
    const float* __restrict__ rel,
    float*       __restrict__ out)
{
    __shared__ float sh[4 * DIM];   // h | t | ch | ct
    __shared__ float wsum[8];

    const int r     = blockIdx.x;
    const int cnt   = g_cnt[r];
    const int is64  = g_is64;
    const int tid   = threadIdx.x;
    const int col   = tid & 127;
    const int half  = tid >> 7;
    const int lane  = tid & 31;
    const int wid   = tid >> 5;

    // Load this relation's matrix into registers (coalesced: consecutive cols).
    float Rreg[64];
    const float* Rp = rel + (size_t)r * (DIM * DIM) + (size_t)(half * 64) * DIM + col;
    #pragma unroll
    for (int k = 0; k < 64; k++) Rreg[k] = Rp[(size_t)k * DIM];

    for (int slot = blockIdx.y; slot < cnt; slot += NSPLIT) {
        const int b = g_list[r * BATCH + slot];

        __syncthreads();  // prior iteration fully done with sh/wsum
        // Gather the 4 entity vectors (512 floats) cooperatively.
        #pragma unroll
        for (int pass = 0; pass < 2; pass++) {
            int idx = tid + pass * 256;
            int w   = idx >> 7;           // 0:h 1:t 2:ch 3:ct
            int off = idx & 127;
            int sel = (w == 0) ? 0 : (w == 1) ? 1 : (w == 2) ? 3 : 4;
            int e   = read_idx(data, b * 5 + sel, is64, N_ENT);
            sh[idx] = ent[(size_t)e * DIM + off];
        }
        __syncthreads();

        float accp = 0.0f, accn = 0.0f;
        const float* hh = sh + half * 64;            // h  rows for my half
        const float* cc = sh + 2 * DIM + half * 64;  // ch rows for my half
        #pragma unroll
        for (int k = 0; k < 64; k += 4) {
            float4 hv = *(const float4*)(hh + k);
            float4 cv = *(const float4*)(cc + k);
            accp = fmaf(hv.x, Rreg[k + 0], accp);
            accn = fmaf(cv.x, Rreg[k + 0], accn);
            accp = fmaf(hv.y, Rreg[k + 1], accp);
            accn = fmaf(cv.y, Rreg[k + 1], accn);
            accp = fmaf(hv.z, Rreg[k + 2], accp);
            accn = fmaf(cv.z, Rreg[k + 2], accn);
            accp = fmaf(hv.w, Rreg[k + 3], accp);
            accn = fmaf(cv.w, Rreg[k + 3], accn);
        }
        float contrib = accp * sh[DIM + col] - accn * sh[3 * DIM + col];

        // Block reduction: pos - neg across 256 threads.
        #pragma unroll
        for (int o = 16; o; o >>= 1)
            contrib += __shfl_xor_sync(0xffffffffu, contrib, o);
        if (lane == 0) wsum[wid] = contrib;
        __syncthreads();
        if (wid == 0) {
            float s = (lane < 8) ? wsum[lane] : 0.0f;
            #pragma unroll
            for (int o = 4; o; o >>= 1)
                s += __shfl_xor_sync(0xffffffffu, s, o);
            if (lane == 0) {
                float v = s + 1.0f;                     // + MARGIN
                if (v > 0.0f) atomicAdd(out, v * (1.0f / BATCH));
            }
        }
    }
}

extern "C" void kernel_launch(void* const* d_in, const int* in_sizes, int n_in,
                              void* d_out, int out_size) {
    const void*  data = d_in[0];
    const float* ent  = (const float*)d_in[1];
    const float* rel  = (const float*)d_in[2];
    float*       out  = (float*)d_out;

    init_kernel<<<1, 256>>>((const unsigned int*)data, out);
    build_kernel<<<(BATCH + 255) / 256, 256>>>(data);
    dim3 grid(N_REL, NSPLIT);
    rescal_kernel<<<grid, 256>>>(data, ent, rel, out);
}